// round 14
// baseline (speedup 1.0000x reference)
#include <cuda_runtime.h>
#include <cuda_bf16.h>

#define NN   50
#define NN2  2500          // N*N
#define ATT  4000          // alpha steps / t-range
#define BB   512           // batch
#define PP   32            // features p
#define NP   (BB * PP)     // 16384 (b,p) pairs
#define CAP  32            // per-t slot capacity (P(overflow) ~ 1e-18)

// Scratch (static __device__ globals: allocation-free rule)
__device__ float g_F[NN2];                   // F = g @ w^2
__device__ int   g_cnt[ATT];                 // per-t pair count (zero-init; self-cleaned by kBC)
__device__ int   g_slot[ATT * CAP];          // pair indices per t
__device__ float g_xT[(size_t)BB * PP * NN]; // xT[b][p][i] (i contiguous)

// ---------------------------------------------------------------------------
// Kernel A (grid 1250 x 256): TWO rows per block. NO smem staging of w:
// the 10KB w vector is read via __ldg (L1-resident per SM after warmup),
// which removes (a) the prologue barrier gating all g loads and (b) the
// 1250-blocks-hammering-80-L2-lines hotspot. Each thread squares w inline.
// Folds in: Z init and hist+scatter (ticket doubles as slot index).
// ---------------------------------------------------------------------------
__global__ void __launch_bounds__(256) kA_F(
        const float* __restrict__ g, const float* __restrict__ w,
        float* __restrict__ outF,
        const int* __restrict__ y_i, const float* __restrict__ mus,
        const int* __restrict__ x_i, float* __restrict__ Z) {
    int tid = threadIdx.x;
    int gid = blockIdx.x * 256 + tid;   // 320000 threads

    if (gid < BB * NN) {
        int b = gid / NN, i = gid - b * NN;
        Z[gid] = (float)PP * mus[(size_t)y_i[b] * NN + i];
    }
    if (gid < NP) {
        int t = x_i[gid];
        int ticket = atomicAdd(&g_cnt[t], 1);
        if (ticket < CAP) g_slot[t * CAP + ticket] = gid;
    }

    int row0 = blockIdx.x * 2;
    const float4* gr0 = (const float4*)(g + (size_t)(row0 + 0) * NN2);
    const float4* gr1 = (const float4*)(g + (size_t)(row0 + 1) * NN2);
    const float4* w4  = (const float4*)w;
    bool p2 = (tid < 625 - 512);         // tid < 113

    // Batched independent g loads (the only DRAM stream); w via L1
    float4 a0 = gr0[tid];
    float4 a1 = gr0[tid + 256];
    float4 a2 = p2 ? gr0[tid + 512] : make_float4(0.f, 0.f, 0.f, 0.f);
    float4 b0 = gr1[tid];
    float4 b1 = gr1[tid + 256];
    float4 b2 = p2 ? gr1[tid + 512] : make_float4(0.f, 0.f, 0.f, 0.f);

    float4 w0 = __ldg(&w4[tid]);
    float4 w1 = __ldg(&w4[tid + 256]);
    float4 w2 = p2 ? __ldg(&w4[tid + 512]) : make_float4(0.f, 0.f, 0.f, 0.f);
    w0 = make_float4(w0.x * w0.x, w0.y * w0.y, w0.z * w0.z, w0.w * w0.w);
    w1 = make_float4(w1.x * w1.x, w1.y * w1.y, w1.z * w1.z, w1.w * w1.w);
    w2 = make_float4(w2.x * w2.x, w2.y * w2.y, w2.z * w2.z, w2.w * w2.w);

    float s0, s1;
    s0  = a0.x * w0.x + a0.y * w0.y + a0.z * w0.z + a0.w * w0.w;
    s0 += a1.x * w1.x + a1.y * w1.y + a1.z * w1.z + a1.w * w1.w;
    s0 += a2.x * w2.x + a2.y * w2.y + a2.z * w2.z + a2.w * w2.w;
    s1  = b0.x * w0.x + b0.y * w0.y + b0.z * w0.z + b0.w * w0.w;
    s1 += b1.x * w1.x + b1.y * w1.y + b1.z * w1.z + b1.w * w1.w;
    s1 += b2.x * w2.x + b2.y * w2.y + b2.z * w2.z + b2.w * w2.w;

    #pragma unroll
    for (int o = 16; o; o >>= 1) {
        s0 += __shfl_down_sync(0xffffffffu, s0, o);
        s1 += __shfl_down_sync(0xffffffffu, s1, o);
    }
    __shared__ float red[2][8];
    int lane = tid & 31, wid = tid >> 5;
    if (lane == 0) { red[0][wid] = s0; red[1][wid] = s1; }
    __syncthreads();
    if (tid < 16) {
        int r = tid >> 3, wx = tid & 7;
        float v = red[r][wx];
        v += __shfl_down_sync(0x0000ffffu, v, 4, 8);
        v += __shfl_down_sync(0x0000ffffu, v, 2, 8);
        v += __shfl_down_sync(0x0000ffffu, v, 1, 8);
        if (wx == 0) { g_F[row0 + r] = v; outF[row0 + r] = v; }
    }
}

// ---------------------------------------------------------------------------
// Kernel T (grid 512 x 256): standalone coalesced x->xT transpose via smem.
// ---------------------------------------------------------------------------
__global__ void kT(const float* __restrict__ x) {
    __shared__ float tile[NN * PP];
    int b = blockIdx.x;
    const float* src = x + (size_t)b * (NN * PP);
    for (int o = threadIdx.x; o < NN * PP; o += 256)
        tile[o] = src[o];                           // coalesced (p fastest)
    __syncthreads();
    float* dst = g_xT + (size_t)b * (PP * NN);
    for (int o = threadIdx.x; o < PP * NN; o += 256) {
        int p = o / NN, i = o - p * NN;
        dst[o] = tile[i * PP + p];                  // coalesced writes
    }
}

// ---------------------------------------------------------------------------
// Kernel BC (grid 4000 x 128): FUSED softmax + apply. One block per t.
// g_F is read via __ldg float4 (L1-resident per SM after the first block),
// killing the 4000-blocks-hammering-the-same-10KB L2 hotspot.
//   - exp phase builds eT[j*50+i] in smem (no global table)
//   - rinv[i] = 1/row-sum; apply to this t's pairs, 4 per pass
//   - self-clean g_cnt[t] = 0 for the next graph replay
// ---------------------------------------------------------------------------
__global__ void kBC(const float* __restrict__ mus, const float* __restrict__ alphas,
                    float* __restrict__ Z) {
    int t = blockIdx.x;
    int cnt = g_cnt[t];
    if (cnt == 0) return;
    if (cnt > CAP) cnt = CAP;

    int tid = threadIdx.x;            // 0..127
    __shared__ float eT[NN2];         // eT[j*50+i]
    __shared__ float rinv_s[NN];
    __shared__ float a_s[4][NN + 2];

    float a = alphas[t];
    const float4* F4 = (const float4*)g_F;    // 625 float4
    for (int c = tid; c < NN2 / 4; c += 128) {
        float4 fv = __ldg(&F4[c]);            // L1 hit after SM warmup
        int idx = c * 4;
        float v0 = __expf(-a * fv.x);
        float v1 = __expf(-a * fv.y);
        float v2 = __expf(-a * fv.z);
        float v3 = __expf(-a * fv.w);
        int i0 = (idx + 0) / NN, j0 = (idx + 0) - i0 * NN;
        int i1 = (idx + 1) / NN, j1 = (idx + 1) - i1 * NN;
        int i2 = (idx + 2) / NN, j2 = (idx + 2) - i2 * NN;
        int i3 = (idx + 3) / NN, j3 = (idx + 3) - i3 * NN;
        eT[j0 * NN + i0] = v0;
        eT[j1 * NN + i1] = v1;
        eT[j2 * NN + i2] = v2;
        eT[j3 * NN + i3] = v3;
    }
    __syncthreads();

    if (tid < NN) {
        float s = 0.f;
        #pragma unroll
        for (int j = 0; j < NN; j++) s += eT[j * NN + tid];   // conflict-free
        rinv_s[tid] = __fdividef(1.0f, s);
    }
    __syncthreads();

    int i = tid;                      // active < 50
    float mu_i = 0.f, rv = 0.f;
    if (i < NN) {
        mu_i = mus[(size_t)t * NN + i];
        rv = rinv_s[i];
    }

    for (int base = 0; base < cnt; base += 4) {
        if (i < NN) {
            #pragma unroll
            for (int k = 0; k < 4; k++) {
                int q = base + k;
                int pr = (q < cnt) ? g_slot[t * CAP + q] : 0;
                a_s[k][i] = g_xT[(size_t)pr * NN + i] - mu_i;
            }
        }
        __syncthreads();
        if (i < NN) {
            float acc0 = 0.f, acc1 = 0.f, acc2 = 0.f, acc3 = 0.f;
            #pragma unroll
            for (int j = 0; j < NN; j++) {
                float f = eT[j * NN + i];        // LDS, conflict-free across lanes
                acc0 += f * a_s[0][j];
                acc1 += f * a_s[1][j];
                acc2 += f * a_s[2][j];
                acc3 += f * a_s[3][j];
            }
            float acc[4] = {acc0, acc1, acc2, acc3};
            #pragma unroll
            for (int k = 0; k < 4; k++) {
                int q = base + k;
                if (q < cnt) {
                    int pr = g_slot[t * CAP + q];
                    int b = pr >> 5;
                    atomicAdd(&Z[b * NN + i], acc[k] * rv);
                }
            }
        }
        __syncthreads();
    }

    if (tid == 0) g_cnt[t] = 0;       // self-clean for next replay
}

// ---------------------------------------------------------------------------
extern "C" void kernel_launch(void* const* d_in, const int* in_sizes, int n_in,
                              void* d_out, int out_size) {
    const float* x      = (const float*)d_in[0];   // [512,50,32]
    const int*   x_i    = (const int*)  d_in[1];   // [512,32]
    const int*   y_i    = (const int*)  d_in[2];   // [512]
    const float* g      = (const float*)d_in[3];   // [2500,2500]
    const float* w      = (const float*)d_in[4];   // [2500,1]
    const float* mus    = (const float*)d_in[5];   // [4000,50]
    const float* alphas = (const float*)d_in[6];   // [4000,1]

    float* Z    = (float*)d_out;        // [512*50]
    float* outF = Z + BB * NN;          // [2500]

    kA_F<<<1250, 256>>>(g, w, outF, y_i, mus, x_i, Z);
    kT<<<BB, 256>>>(x);
    kBC<<<ATT, 128>>>(mus, alphas, Z);
}

// round 15
// speedup vs baseline: 1.0696x; 1.0696x over previous
#include <cuda_runtime.h>
#include <cuda_bf16.h>

#define NN   50
#define NN2  2500          // N*N
#define ATT  4000          // alpha steps / t-range
#define BB   512           // batch
#define PP   32            // features p
#define NP   (BB * PP)     // 16384 (b,p) pairs
#define CAP  32            // per-t slot capacity (P(overflow) ~ 1e-18)

// Scratch (static __device__ globals: allocation-free rule)
__device__ float g_F[NN2];                   // F = g @ w^2 (row-major, for output)
__device__ float g_FT[NN2];                  // F transposed: g_FT[j*50+i] = F[i*50+j]
__device__ int   g_cnt[ATT];                 // per-t pair count (zero-init; self-cleaned by kBC)
__device__ int   g_slot[ATT * CAP];          // pair indices per t
__device__ float g_xT[(size_t)BB * PP * NN]; // xT[b][p][i] (i contiguous)

// ---------------------------------------------------------------------------
// Kernel A (grid 1250 x 256): TWO rows per block; w via __ldg (L1), squared
// inline; 6 batched independent g LDG.128s per thread. Writes F both
// row-major (output) and TRANSPOSED (g_FT) so kBC's exp loop needs zero
// index arithmetic. Folds in: Z init and hist+scatter.
// ---------------------------------------------------------------------------
__global__ void __launch_bounds__(256) kA_F(
        const float* __restrict__ g, const float* __restrict__ w,
        float* __restrict__ outF,
        const int* __restrict__ y_i, const float* __restrict__ mus,
        const int* __restrict__ x_i, float* __restrict__ Z) {
    int tid = threadIdx.x;
    int gid = blockIdx.x * 256 + tid;   // 320000 threads

    if (gid < BB * NN) {
        int b = gid / NN, i = gid - b * NN;
        Z[gid] = (float)PP * mus[(size_t)y_i[b] * NN + i];
    }
    if (gid < NP) {
        int t = x_i[gid];
        int ticket = atomicAdd(&g_cnt[t], 1);
        if (ticket < CAP) g_slot[t * CAP + ticket] = gid;
    }

    int row0 = blockIdx.x * 2;
    const float4* gr0 = (const float4*)(g + (size_t)(row0 + 0) * NN2);
    const float4* gr1 = (const float4*)(g + (size_t)(row0 + 1) * NN2);
    const float4* w4  = (const float4*)w;
    bool p2 = (tid < 625 - 512);         // tid < 113

    float4 a0 = gr0[tid];
    float4 a1 = gr0[tid + 256];
    float4 a2 = p2 ? gr0[tid + 512] : make_float4(0.f, 0.f, 0.f, 0.f);
    float4 b0 = gr1[tid];
    float4 b1 = gr1[tid + 256];
    float4 b2 = p2 ? gr1[tid + 512] : make_float4(0.f, 0.f, 0.f, 0.f);

    float4 w0 = __ldg(&w4[tid]);
    float4 w1 = __ldg(&w4[tid + 256]);
    float4 w2 = p2 ? __ldg(&w4[tid + 512]) : make_float4(0.f, 0.f, 0.f, 0.f);
    w0 = make_float4(w0.x * w0.x, w0.y * w0.y, w0.z * w0.z, w0.w * w0.w);
    w1 = make_float4(w1.x * w1.x, w1.y * w1.y, w1.z * w1.z, w1.w * w1.w);
    w2 = make_float4(w2.x * w2.x, w2.y * w2.y, w2.z * w2.z, w2.w * w2.w);

    float s0, s1;
    s0  = a0.x * w0.x + a0.y * w0.y + a0.z * w0.z + a0.w * w0.w;
    s0 += a1.x * w1.x + a1.y * w1.y + a1.z * w1.z + a1.w * w1.w;
    s0 += a2.x * w2.x + a2.y * w2.y + a2.z * w2.z + a2.w * w2.w;
    s1  = b0.x * w0.x + b0.y * w0.y + b0.z * w0.z + b0.w * w0.w;
    s1 += b1.x * w1.x + b1.y * w1.y + b1.z * w1.z + b1.w * w1.w;
    s1 += b2.x * w2.x + b2.y * w2.y + b2.z * w2.z + b2.w * w2.w;

    #pragma unroll
    for (int o = 16; o; o >>= 1) {
        s0 += __shfl_down_sync(0xffffffffu, s0, o);
        s1 += __shfl_down_sync(0xffffffffu, s1, o);
    }
    __shared__ float red[2][8];
    int lane = tid & 31, wid = tid >> 5;
    if (lane == 0) { red[0][wid] = s0; red[1][wid] = s1; }
    __syncthreads();
    if (tid < 16) {
        int r = tid >> 3, wx = tid & 7;
        float v = red[r][wx];
        v += __shfl_down_sync(0x0000ffffu, v, 4, 8);
        v += __shfl_down_sync(0x0000ffffu, v, 2, 8);
        v += __shfl_down_sync(0x0000ffffu, v, 1, 8);
        if (wx == 0) {
            int rr = row0 + r;
            g_F[rr] = v; outF[rr] = v;
            int ii = rr / NN, jj = rr - ii * NN;
            g_FT[jj * NN + ii] = v;          // transposed copy for kBC
        }
    }
}

// ---------------------------------------------------------------------------
// Kernel T (grid 512 x 256): standalone coalesced x->xT transpose via smem.
// ---------------------------------------------------------------------------
__global__ void kT(const float* __restrict__ x) {
    __shared__ float tile[NN * PP];
    int b = blockIdx.x;
    const float* src = x + (size_t)b * (NN * PP);
    for (int o = threadIdx.x; o < NN * PP; o += 256)
        tile[o] = src[o];                           // coalesced (p fastest)
    __syncthreads();
    float* dst = g_xT + (size_t)b * (PP * NN);
    for (int o = threadIdx.x; o < PP * NN; o += 256) {
        int p = o / NN, i = o - p * NN;
        dst[o] = tile[i * PP + p];                  // coalesced writes
    }
}

// ---------------------------------------------------------------------------
// Kernel BC (grid 4000 x 128): FUSED softmax + apply, one block per t.
// Exp phase is now STRAIGHT-LINE: g_FT is already transposed, so
//   eT4[c] = exp(-a * FT4[c])   (LDG.128 + 4 EX2 + STS.128; no index math,
// no scattered stores). ~10x fewer instructions than the idx/50-idx%50 form.
//   - rinv[i] = 1/row-sum; apply to this t's pairs, 4 per pass
//   - self-clean g_cnt[t] = 0 for the next graph replay
// ---------------------------------------------------------------------------
__global__ void kBC(const float* __restrict__ mus, const float* __restrict__ alphas,
                    float* __restrict__ Z) {
    int t = blockIdx.x;
    int cnt = g_cnt[t];
    if (cnt == 0) return;
    if (cnt > CAP) cnt = CAP;

    int tid = threadIdx.x;            // 0..127
    __shared__ float eT[NN2];         // eT[j*50+i]
    __shared__ float rinv_s[NN];
    __shared__ float a_s[4][NN + 2];

    float a = alphas[t];
    const float4* FT4 = (const float4*)g_FT;  // 625 float4, already transposed
    float4* eT4 = (float4*)eT;
    #pragma unroll
    for (int k = 0; k < 5; k++) {
        int c = tid + (k << 7);               // tid + k*128
        if (c < NN2 / 4) {
            float4 fv = __ldg(&FT4[c]);
            float4 ev;
            ev.x = __expf(-a * fv.x);
            ev.y = __expf(-a * fv.y);
            ev.z = __expf(-a * fv.z);
            ev.w = __expf(-a * fv.w);
            eT4[c] = ev;                      // STS.128, conflict-free
        }
    }
    __syncthreads();

    if (tid < NN) {
        float s = 0.f;
        #pragma unroll
        for (int j = 0; j < NN; j++) s += eT[j * NN + tid];
        rinv_s[tid] = __fdividef(1.0f, s);
    }
    __syncthreads();

    int i = tid;                      // active < 50
    float mu_i = 0.f, rv = 0.f;
    if (i < NN) {
        mu_i = mus[(size_t)t * NN + i];
        rv = rinv_s[i];
    }

    for (int base = 0; base < cnt; base += 4) {
        if (i < NN) {
            #pragma unroll
            for (int k = 0; k < 4; k++) {
                int q = base + k;
                int pr = (q < cnt) ? g_slot[t * CAP + q] : 0;
                a_s[k][i] = g_xT[(size_t)pr * NN + i] - mu_i;
            }
        }
        __syncthreads();
        if (i < NN) {
            float acc0 = 0.f, acc1 = 0.f, acc2 = 0.f, acc3 = 0.f;
            #pragma unroll
            for (int j = 0; j < NN; j++) {
                float f = eT[j * NN + i];
                acc0 += f * a_s[0][j];
                acc1 += f * a_s[1][j];
                acc2 += f * a_s[2][j];
                acc3 += f * a_s[3][j];
            }
            float acc[4] = {acc0, acc1, acc2, acc3};
            #pragma unroll
            for (int k = 0; k < 4; k++) {
                int q = base + k;
                if (q < cnt) {
                    int pr = g_slot[t * CAP + q];
                    int b = pr >> 5;
                    atomicAdd(&Z[b * NN + i], acc[k] * rv);
                }
            }
        }
        __syncthreads();
    }

    if (tid == 0) g_cnt[t] = 0;       // self-clean for next replay
}

// ---------------------------------------------------------------------------
extern "C" void kernel_launch(void* const* d_in, const int* in_sizes, int n_in,
                              void* d_out, int out_size) {
    const float* x      = (const float*)d_in[0];   // [512,50,32]
    const int*   x_i    = (const int*)  d_in[1];   // [512,32]
    const int*   y_i    = (const int*)  d_in[2];   // [512]
    const float* g      = (const float*)d_in[3];   // [2500,2500]
    const float* w      = (const float*)d_in[4];   // [2500,1]
    const float* mus    = (const float*)d_in[5];   // [4000,50]
    const float* alphas = (const float*)d_in[6];   // [4000,1]

    float* Z    = (float*)d_out;        // [512*50]
    float* outF = Z + BB * NN;          // [2500]

    kA_F<<<1250, 256>>>(g, w, outF, y_i, mus, x_i, Z);
    kT<<<BB, 256>>>(x);
    kBC<<<ATT, 128>>>(mus, alphas, Z);
}

// round 16
// speedup vs baseline: 1.0971x; 1.0257x over previous
#include <cuda_runtime.h>
#include <cuda_bf16.h>

#define NN   50
#define NN2  2500          // N*N
#define ATT  4000          // alpha steps / t-range
#define BB   512           // batch
#define PP   32            // features p
#define NP   (BB * PP)     // 16384 (b,p) pairs
#define CAP  32            // per-t slot capacity (P(overflow) ~ 1e-18)

// Scratch (static __device__ globals: allocation-free rule)
__device__ float g_F[NN2];                   // F = g @ w^2 (row-major, for output)
__device__ float g_FT[NN2];                  // F transposed: g_FT[j*50+i] = F[i*50+j]
__device__ int   g_cnt[ATT];                 // per-t pair count (zero-init; self-cleaned by kBC)
__device__ int   g_slot[ATT * CAP];          // pair indices per t
__device__ float g_xT[(size_t)BB * PP * NN]; // xT[b][p][i] (i contiguous)

// ---------------------------------------------------------------------------
// Kernel A (grid 1250 x 256): TWO rows per block; w via __ldg (L1), squared
// inline; 6 batched independent g LDG.128s per thread. Writes F row-major
// (output) and transposed (g_FT). Folds in: Z init and hist+scatter.
// ---------------------------------------------------------------------------
__global__ void __launch_bounds__(256) kA_F(
        const float* __restrict__ g, const float* __restrict__ w,
        float* __restrict__ outF,
        const int* __restrict__ y_i, const float* __restrict__ mus,
        const int* __restrict__ x_i, float* __restrict__ Z) {
    int tid = threadIdx.x;
    int gid = blockIdx.x * 256 + tid;   // 320000 threads

    if (gid < BB * NN) {
        int b = gid / NN, i = gid - b * NN;
        Z[gid] = (float)PP * mus[(size_t)y_i[b] * NN + i];
    }
    if (gid < NP) {
        int t = x_i[gid];
        int ticket = atomicAdd(&g_cnt[t], 1);
        if (ticket < CAP) g_slot[t * CAP + ticket] = gid;
    }

    int row0 = blockIdx.x * 2;
    const float4* gr0 = (const float4*)(g + (size_t)(row0 + 0) * NN2);
    const float4* gr1 = (const float4*)(g + (size_t)(row0 + 1) * NN2);
    const float4* w4  = (const float4*)w;
    bool p2 = (tid < 625 - 512);         // tid < 113

    float4 a0 = gr0[tid];
    float4 a1 = gr0[tid + 256];
    float4 a2 = p2 ? gr0[tid + 512] : make_float4(0.f, 0.f, 0.f, 0.f);
    float4 b0 = gr1[tid];
    float4 b1 = gr1[tid + 256];
    float4 b2 = p2 ? gr1[tid + 512] : make_float4(0.f, 0.f, 0.f, 0.f);

    float4 w0 = __ldg(&w4[tid]);
    float4 w1 = __ldg(&w4[tid + 256]);
    float4 w2 = p2 ? __ldg(&w4[tid + 512]) : make_float4(0.f, 0.f, 0.f, 0.f);
    w0 = make_float4(w0.x * w0.x, w0.y * w0.y, w0.z * w0.z, w0.w * w0.w);
    w1 = make_float4(w1.x * w1.x, w1.y * w1.y, w1.z * w1.z, w1.w * w1.w);
    w2 = make_float4(w2.x * w2.x, w2.y * w2.y, w2.z * w2.z, w2.w * w2.w);

    float s0, s1;
    s0  = a0.x * w0.x + a0.y * w0.y + a0.z * w0.z + a0.w * w0.w;
    s0 += a1.x * w1.x + a1.y * w1.y + a1.z * w1.z + a1.w * w1.w;
    s0 += a2.x * w2.x + a2.y * w2.y + a2.z * w2.z + a2.w * w2.w;
    s1  = b0.x * w0.x + b0.y * w0.y + b0.z * w0.z + b0.w * w0.w;
    s1 += b1.x * w1.x + b1.y * w1.y + b1.z * w1.z + b1.w * w1.w;
    s1 += b2.x * w2.x + b2.y * w2.y + b2.z * w2.z + b2.w * w2.w;

    #pragma unroll
    for (int o = 16; o; o >>= 1) {
        s0 += __shfl_down_sync(0xffffffffu, s0, o);
        s1 += __shfl_down_sync(0xffffffffu, s1, o);
    }
    __shared__ float red[2][8];
    int lane = tid & 31, wid = tid >> 5;
    if (lane == 0) { red[0][wid] = s0; red[1][wid] = s1; }
    __syncthreads();
    if (tid < 16) {
        int r = tid >> 3, wx = tid & 7;
        float v = red[r][wx];
        v += __shfl_down_sync(0x0000ffffu, v, 4, 8);
        v += __shfl_down_sync(0x0000ffffu, v, 2, 8);
        v += __shfl_down_sync(0x0000ffffu, v, 1, 8);
        if (wx == 0) {
            int rr = row0 + r;
            g_F[rr] = v; outF[rr] = v;
            int ii = rr / NN, jj = rr - ii * NN;
            g_FT[jj * NN + ii] = v;          // transposed copy for kBC
        }
    }
}

// ---------------------------------------------------------------------------
// Kernel T (grid 512 x 256): coalesced x->xT transpose via smem.
// Runs CONCURRENTLY with kA on a second captured stream (only kBC needs both).
// ---------------------------------------------------------------------------
__global__ void kT(const float* __restrict__ x) {
    __shared__ float tile[NN * PP];
    int b = blockIdx.x;
    const float* src = x + (size_t)b * (NN * PP);
    for (int o = threadIdx.x; o < NN * PP; o += 256)
        tile[o] = src[o];                           // coalesced (p fastest)
    __syncthreads();
    float* dst = g_xT + (size_t)b * (PP * NN);
    for (int o = threadIdx.x; o < PP * NN; o += 256) {
        int p = o / NN, i = o - p * NN;
        dst[o] = tile[i * PP + p];                  // coalesced writes
    }
}

// ---------------------------------------------------------------------------
// Kernel BC (grid 4000 x 128): FUSED softmax + apply, one block per t.
// cnt load is issued first but only consumed AFTER the exp+rowsum phases
// (which every block needs anyway), keeping the block prologue latency-free.
// Exp phase is straight-line over pre-transposed g_FT.
// ---------------------------------------------------------------------------
__global__ void kBC(const float* __restrict__ mus, const float* __restrict__ alphas,
                    float* __restrict__ Z) {
    int t = blockIdx.x;
    int tid = threadIdx.x;            // 0..127

    int cnt = g_cnt[t];               // issued now, consumed after exp phase

    __shared__ float eT[NN2];         // eT[j*50+i]
    __shared__ float rinv_s[NN];
    __shared__ float a_s[4][NN + 2];

    float a = alphas[t];
    const float4* FT4 = (const float4*)g_FT;  // 625 float4, already transposed
    float4* eT4 = (float4*)eT;
    #pragma unroll
    for (int k = 0; k < 5; k++) {
        int c = tid + (k << 7);               // tid + k*128
        if (c < NN2 / 4) {
            float4 fv = __ldg(&FT4[c]);
            float4 ev;
            ev.x = __expf(-a * fv.x);
            ev.y = __expf(-a * fv.y);
            ev.z = __expf(-a * fv.z);
            ev.w = __expf(-a * fv.w);
            eT4[c] = ev;                      // STS.128, conflict-free
        }
    }
    __syncthreads();

    if (tid < NN) {
        float s = 0.f;
        #pragma unroll
        for (int j = 0; j < NN; j++) s += eT[j * NN + tid];
        rinv_s[tid] = __fdividef(1.0f, s);
    }
    __syncthreads();

    if (cnt == 0) return;             // uniform exit after the last barrier use
    if (cnt > CAP) cnt = CAP;

    int i = tid;                      // active < 50
    float mu_i = 0.f, rv = 0.f;
    if (i < NN) {
        mu_i = mus[(size_t)t * NN + i];
        rv = rinv_s[i];
    }

    for (int base = 0; base < cnt; base += 4) {
        if (i < NN) {
            #pragma unroll
            for (int k = 0; k < 4; k++) {
                int q = base + k;
                int pr = (q < cnt) ? g_slot[t * CAP + q] : 0;
                a_s[k][i] = g_xT[(size_t)pr * NN + i] - mu_i;
            }
        }
        __syncthreads();
        if (i < NN) {
            float acc0 = 0.f, acc1 = 0.f, acc2 = 0.f, acc3 = 0.f;
            #pragma unroll
            for (int j = 0; j < NN; j++) {
                float f = eT[j * NN + i];
                acc0 += f * a_s[0][j];
                acc1 += f * a_s[1][j];
                acc2 += f * a_s[2][j];
                acc3 += f * a_s[3][j];
            }
            float acc[4] = {acc0, acc1, acc2, acc3};
            #pragma unroll
            for (int k = 0; k < 4; k++) {
                int q = base + k;
                if (q < cnt) {
                    int pr = g_slot[t * CAP + q];
                    int b = pr >> 5;
                    atomicAdd(&Z[b * NN + i], acc[k] * rv);
                }
            }
        }
        __syncthreads();
    }

    if (tid == 0) g_cnt[t] = 0;       // self-clean for next replay
}

// ---------------------------------------------------------------------------
extern "C" void kernel_launch(void* const* d_in, const int* in_sizes, int n_in,
                              void* d_out, int out_size) {
    const float* x      = (const float*)d_in[0];   // [512,50,32]
    const int*   x_i    = (const int*)  d_in[1];   // [512,32]
    const int*   y_i    = (const int*)  d_in[2];   // [512]
    const float* g      = (const float*)d_in[3];   // [2500,2500]
    const float* w      = (const float*)d_in[4];   // [2500,1]
    const float* mus    = (const float*)d_in[5];   // [4000,50]
    const float* alphas = (const float*)d_in[6];   // [4000,1]

    float* Z    = (float*)d_out;        // [512*50]
    float* outF = Z + BB * NN;          // [2500]

    // One-time stream/event setup (host-side objects; no device allocations,
    // no captured work depends on this — the captured graph is identical on
    // every call).
    static cudaStream_t s2 = nullptr;
    static cudaEvent_t  evFork = nullptr, evJoin = nullptr;
    if (s2 == nullptr) {
        cudaStreamCreateWithFlags(&s2, cudaStreamNonBlocking);
        cudaEventCreateWithFlags(&evFork, cudaEventDisableTiming);
        cudaEventCreateWithFlags(&evJoin, cudaEventDisableTiming);
    }

    // Fork: kT (x transpose) runs concurrently with kA on stream s2.
    cudaEventRecord(evFork, 0);
    cudaStreamWaitEvent(s2, evFork, 0);
    kT<<<BB, 256, 0, s2>>>(x);
    kA_F<<<1250, 256>>>(g, w, outF, y_i, mus, x_i, Z);
    // Join: kBC needs both g_F/g_FT (kA) and g_xT (kT).
    cudaEventRecord(evJoin, s2);
    cudaStreamWaitEvent(0, evJoin, 0);
    kBC<<<ATT, 128>>>(mus, alphas, Z);
}

// round 17
// speedup vs baseline: 1.2427x; 1.1327x over previous
#include <cuda_runtime.h>
#include <cuda_bf16.h>

#define NN   50
#define NN2  2500          // N*N
#define ATT  4000          // alpha steps / t-range
#define BB   512           // batch
#define PP   32            // features p
#define NP   (BB * PP)     // 16384 (b,p) pairs
#define CAP  32            // per-t slot capacity (P(overflow) ~ 1e-18)
#define MVB  1762          // kA grid: 512 transpose blocks + 1250 matvec blocks

// Scratch (static __device__ globals: allocation-free rule)
__device__ float g_F[NN2];                   // F = g @ w^2 (row-major)
__device__ int   g_cnt[ATT];                 // per-t pair count (zero-init; self-cleaned by kBC)
__device__ int   g_slot[ATT * CAP];          // pair indices per t
__device__ float g_xT[(size_t)BB * PP * NN]; // xT[b][p][i] (i contiguous)

// ---------------------------------------------------------------------------
// Kernel A (grid 1762 x 256): blocks 0..511 do the x->xT transpose (scheduled
// first so they drain early); blocks 512..1761 do TWO matvec rows each
// (w via __ldg L1, squared inline; 6 batched independent g LDG.128s).
// Z init + hist/scatter ride on the early (transpose) blocks' gid range.
// ---------------------------------------------------------------------------
__global__ void __launch_bounds__(256) kA_F(
        const float* __restrict__ g, const float* __restrict__ w,
        float* __restrict__ outF,
        const int* __restrict__ y_i, const float* __restrict__ mus,
        const int* __restrict__ x_i, const float* __restrict__ x,
        float* __restrict__ Z) {
    int tid = threadIdx.x;
    int bid = blockIdx.x;
    int gid = bid * 256 + tid;

    if (gid < BB * NN) {
        int b = gid / NN, i = gid - b * NN;
        Z[gid] = (float)PP * mus[(size_t)y_i[b] * NN + i];
    }
    if (gid < NP) {
        int t = x_i[gid];
        int ticket = atomicAdd(&g_cnt[t], 1);
        if (ticket < CAP) g_slot[t * CAP + ticket] = gid;
    }

    if (bid < BB) {
        // ---- transpose block: x[b][50][32] -> xT[b][32][50] via smem tile
        __shared__ float tile[NN * PP];
        const float* src = x + (size_t)bid * (NN * PP);
        for (int o = tid; o < NN * PP; o += 256)
            tile[o] = src[o];                       // coalesced (p fastest)
        __syncthreads();
        float* dst = g_xT + (size_t)bid * (PP * NN);
        for (int o = tid; o < PP * NN; o += 256) {
            int p = o / NN, i = o - p * NN;
            dst[o] = tile[i * PP + p];              // coalesced writes
        }
        return;
    }

    // ---- matvec block
    int row0 = (bid - BB) * 2;
    const float4* gr0 = (const float4*)(g + (size_t)(row0 + 0) * NN2);
    const float4* gr1 = (const float4*)(g + (size_t)(row0 + 1) * NN2);
    const float4* w4  = (const float4*)w;
    bool p2 = (tid < 625 - 512);         // tid < 113

    float4 a0 = gr0[tid];
    float4 a1 = gr0[tid + 256];
    float4 a2 = p2 ? gr0[tid + 512] : make_float4(0.f, 0.f, 0.f, 0.f);
    float4 b0 = gr1[tid];
    float4 b1 = gr1[tid + 256];
    float4 b2 = p2 ? gr1[tid + 512] : make_float4(0.f, 0.f, 0.f, 0.f);

    float4 w0 = __ldg(&w4[tid]);
    float4 w1 = __ldg(&w4[tid + 256]);
    float4 w2 = p2 ? __ldg(&w4[tid + 512]) : make_float4(0.f, 0.f, 0.f, 0.f);
    w0 = make_float4(w0.x * w0.x, w0.y * w0.y, w0.z * w0.z, w0.w * w0.w);
    w1 = make_float4(w1.x * w1.x, w1.y * w1.y, w1.z * w1.z, w1.w * w1.w);
    w2 = make_float4(w2.x * w2.x, w2.y * w2.y, w2.z * w2.z, w2.w * w2.w);

    float s0, s1;
    s0  = a0.x * w0.x + a0.y * w0.y + a0.z * w0.z + a0.w * w0.w;
    s0 += a1.x * w1.x + a1.y * w1.y + a1.z * w1.z + a1.w * w1.w;
    s0 += a2.x * w2.x + a2.y * w2.y + a2.z * w2.z + a2.w * w2.w;
    s1  = b0.x * w0.x + b0.y * w0.y + b0.z * w0.z + b0.w * w0.w;
    s1 += b1.x * w1.x + b1.y * w1.y + b1.z * w1.z + b1.w * w1.w;
    s1 += b2.x * w2.x + b2.y * w2.y + b2.z * w2.z + b2.w * w2.w;

    #pragma unroll
    for (int o = 16; o; o >>= 1) {
        s0 += __shfl_down_sync(0xffffffffu, s0, o);
        s1 += __shfl_down_sync(0xffffffffu, s1, o);
    }
    __shared__ float red[2][8];
    int lane = tid & 31, wid = tid >> 5;
    if (lane == 0) { red[0][wid] = s0; red[1][wid] = s1; }
    __syncthreads();
    if (tid < 16) {
        int r = tid >> 3, wx = tid & 7;
        float v = red[r][wx];
        v += __shfl_down_sync(0x0000ffffu, v, 4, 8);
        v += __shfl_down_sync(0x0000ffffu, v, 2, 8);
        v += __shfl_down_sync(0x0000ffffu, v, 1, 8);
        if (wx == 0) {
            int rr = row0 + r;
            g_F[rr] = v; outF[rr] = v;
        }
    }
}

// ---------------------------------------------------------------------------
// Kernel BC (grid 4000 x 64): REGISTER-RESIDENT softmax + apply, one block/t.
// Thread i owns output row i entirely:
//   - loads its contiguous g_F row (25 float2, L1-hot 10KB table)
//   - computes 50 exps into registers, sums in-register, pre-scales by rinv
//     -> NO eT smem, NO rowsum phase, NO exp/rowsum barriers
//   - apply: 4 pairs per pass from a_s smem broadcast (proven structure)
//   - self-cleans g_cnt[t] for the next graph replay
// ---------------------------------------------------------------------------
__global__ void kBC(const float* __restrict__ mus, const float* __restrict__ alphas,
                    float* __restrict__ Z) {
    int t = blockIdx.x;
    int tid = threadIdx.x;            // 0..63, active < 50

    int cnt = g_cnt[t];
    if (cnt == 0) return;             // uniform (pre-barrier) exit
    if (cnt > CAP) cnt = CAP;

    float a = alphas[t];
    float f[NN];
    float mu_i = 0.f;
    int i = tid;

    if (i < NN) {
        mu_i = mus[(size_t)t * NN + i];
        const float2* Fr = (const float2*)(g_F + i * NN);   // 200B row, 8B aligned
        float sA = 0.f, sB = 0.f;
        #pragma unroll
        for (int k = 0; k < 25; k++) {
            float2 v = __ldg(&Fr[k]);
            float e0 = __expf(-a * v.x);
            float e1 = __expf(-a * v.y);
            f[2 * k]     = e0;
            f[2 * k + 1] = e1;
            sA += e0; sB += e1;
        }
        float rinv = __fdividef(1.0f, sA + sB);
        #pragma unroll
        for (int j = 0; j < NN; j++) f[j] *= rinv;          // fold rinv into f
    }

    __shared__ float a_s[4][NN + 2];

    for (int base = 0; base < cnt; base += 4) {
        if (i < NN) {
            #pragma unroll
            for (int k = 0; k < 4; k++) {
                int q = base + k;
                int pr = (q < cnt) ? g_slot[t * CAP + q] : 0;
                a_s[k][i] = g_xT[(size_t)pr * NN + i] - mu_i;
            }
        }
        __syncthreads();
        if (i < NN) {
            float acc0 = 0.f, acc1 = 0.f, acc2 = 0.f, acc3 = 0.f;
            #pragma unroll
            for (int j = 0; j < NN; j++) {
                float fj = f[j];
                acc0 += fj * a_s[0][j];
                acc1 += fj * a_s[1][j];
                acc2 += fj * a_s[2][j];
                acc3 += fj * a_s[3][j];
            }
            float acc[4] = {acc0, acc1, acc2, acc3};
            #pragma unroll
            for (int k = 0; k < 4; k++) {
                int q = base + k;
                if (q < cnt) {
                    int pr = g_slot[t * CAP + q];
                    int b = pr >> 5;
                    atomicAdd(&Z[b * NN + i], acc[k]);
                }
            }
        }
        __syncthreads();
    }

    if (tid == 0) g_cnt[t] = 0;       // self-clean for next replay
}

// ---------------------------------------------------------------------------
extern "C" void kernel_launch(void* const* d_in, const int* in_sizes, int n_in,
                              void* d_out, int out_size) {
    const float* x      = (const float*)d_in[0];   // [512,50,32]
    const int*   x_i    = (const int*)  d_in[1];   // [512,32]
    const int*   y_i    = (const int*)  d_in[2];   // [512]
    const float* g      = (const float*)d_in[3];   // [2500,2500]
    const float* w      = (const float*)d_in[4];   // [2500,1]
    const float* mus    = (const float*)d_in[5];   // [4000,50]
    const float* alphas = (const float*)d_in[6];   // [4000,1]

    float* Z    = (float*)d_out;        // [512*50]
    float* outF = Z + BB * NN;          // [2500]

    kA_F<<<MVB, 256>>>(g, w, outF, y_i, mus, x_i, x, Z);
    kBC<<<ATT, 64>>>(mus, alphas, Z);
}